// round 1
// baseline (speedup 1.0000x reference)
#include <cuda_runtime.h>
#include <math.h>

#define TT 49
#define UNITS 256
#define QN 9
#define DIMF 256
#define BATCH 2048
#define G4 1024   // 4 gates * UNITS
#define PI_F 3.14159265358979f

// ---- static device scratch (allocation-free contract) ----
__device__ float g_U[(size_t)TT * UNITS * UNITS];          // 12.8 MB  [t][i][j]
__device__ float g_Whc[(size_t)UNITS * G4];                // c-part weights [k][g*256+j]
__device__ float g_Whx[(size_t)DIMF * G4];                 // x-part weights [k][g*256+j]
__device__ float g_Xp[(size_t)BATCH * TT * G4];            // 411 MB  [(b*T+t)][n]
__device__ float g_S[(size_t)BATCH * TT * UNITS];          // 103 MB  [(b*T+t)][i]

__device__ __forceinline__ float sigf(float x) {
    return 1.0f / (1.0f + expf(-x));
}

// ---------------------------------------------------------------------------
// U[t][i][j] = sum_q Q[i, j*9+q] * B[t][q], Fourier basis on linspace(0,1,49)
// grid (TT, UNITS), block 256 (j)
// ---------------------------------------------------------------------------
__global__ void build_U(const float* __restrict__ Q) {
    int t = blockIdx.x;
    int i = blockIdx.y;
    int j = threadIdx.x;
    __shared__ float Bq[QN];
    if (threadIdx.x < QN) {
        int q = threadIdx.x;
        float tt = (float)t / (float)(TT - 1);
        float v;
        if (q == 0) {
            v = 1.0f;
        } else {
            int h = (q + 1) >> 1;                 // harmonic 1..4
            float w = 2.0f * PI_F * (float)h * tt;
            v = 1.41421356237309515f * ((q & 1) ? sinf(w) : cosf(w));
        }
        Bq[q] = v;
    }
    __syncthreads();
    const float* qrow = Q + (size_t)i * (UNITS * QN) + (size_t)j * QN;
    float acc = 0.0f;
#pragma unroll
    for (int q = 0; q < QN; q++) acc = fmaf(qrow[q], Bq[q], acc);
    g_U[((size_t)t * UNITS + i) * UNITS + j] = acc;
}

// ---------------------------------------------------------------------------
// Rearrange weights: rows 0..255 -> Whc, rows 256..511 -> Whx, cols [g*256+j]
// ---------------------------------------------------------------------------
__global__ void prep_W(const float* __restrict__ Wf, const float* __restrict__ Wi,
                       const float* __restrict__ Wc, const float* __restrict__ Wo) {
    int idx = blockIdx.x * blockDim.x + threadIdx.x;
    if (idx >= 512 * UNITS) return;
    int k = idx / UNITS;
    int j = idx % UNITS;
    float vf = Wf[idx], vi = Wi[idx], vc = Wc[idx], vo = Wo[idx];
    float* dst = (k < UNITS) ? (g_Whc + (size_t)k * G4)
                             : (g_Whx + (size_t)(k - UNITS) * G4);
    dst[0 * UNITS + j] = vf;
    dst[1 * UNITS + j] = vi;
    dst[2 * UNITS + j] = vc;
    dst[3 * UNITS + j] = vo;
}

// ---------------------------------------------------------------------------
// Xp = X(100352 x 256) @ Whx(256 x 1024).  64x64 tile, 256 thr, 4x4/thread.
// ---------------------------------------------------------------------------
__global__ __launch_bounds__(256) void gemm_xproj(const float* __restrict__ A) {
    __shared__ float As[16][64];
    __shared__ float Bs[16][64];
    int tid = threadIdx.x;
    int bm = blockIdx.x, bn = blockIdx.y;
    int tx = tid & 15, ty = tid >> 4;

    const float* Ab = A + (size_t)bm * 64 * DIMF;
    const float* Bb = g_Whx + (size_t)bn * 64;

    int arow = tid >> 2;            // 0..63
    int acol = (tid & 3) * 4;       // 0,4,8,12
    int brow = tid >> 4;            // 0..15
    int bcol = (tid & 15) * 4;      // 0..60

    float acc[4][4] = {};

    for (int k0 = 0; k0 < DIMF; k0 += 16) {
        float4 av = *(const float4*)(Ab + (size_t)arow * DIMF + k0 + acol);
        float4 bv = *(const float4*)(Bb + (size_t)(k0 + brow) * G4 + bcol);
        __syncthreads();
        As[acol + 0][arow] = av.x;
        As[acol + 1][arow] = av.y;
        As[acol + 2][arow] = av.z;
        As[acol + 3][arow] = av.w;
        *(float4*)&Bs[brow][bcol] = bv;
        __syncthreads();
#pragma unroll
        for (int k = 0; k < 16; k++) {
            float4 a = *(const float4*)&As[k][ty * 4];
            float4 b = *(const float4*)&Bs[k][tx * 4];
            float ar[4] = {a.x, a.y, a.z, a.w};
            float br[4] = {b.x, b.y, b.z, b.w};
#pragma unroll
            for (int r = 0; r < 4; r++)
#pragma unroll
                for (int c = 0; c < 4; c++)
                    acc[r][c] = fmaf(ar[r], br[c], acc[r][c]);
        }
    }
    float* Cb = g_Xp + (size_t)bm * 64 * G4 + (size_t)bn * 64;
#pragma unroll
    for (int r = 0; r < 4; r++) {
        float4 o = make_float4(acc[r][0], acc[r][1], acc[r][2], acc[r][3]);
        *(float4*)(Cb + (size_t)(ty * 4 + r) * G4 + tx * 4) = o;
    }
}

// ---------------------------------------------------------------------------
// Recurrence: 128 blocks x 16 batch rows each, t-loop internal, c in smem.
// Per step: gates(16x1024) = c(16x256) @ Whc(256x1024) + Xp;  c_new; s -> g_S.
// ---------------------------------------------------------------------------
__global__ __launch_bounds__(256) void recur() {
    int b0 = blockIdx.x * 16;
    int tid = threadIdx.x;
    __shared__ float cs[16][UNITS];   // 16 KB

#pragma unroll
    for (int r = 0; r < 16; r++) cs[r][tid] = 0.0f;

    for (int t = 0; t < TT; t++) {
        __syncthreads();              // cs writes from prev step visible

        float acc[16][4];
#pragma unroll
        for (int r = 0; r < 16; r++)
#pragma unroll
            for (int g = 0; g < 4; g++) acc[r][g] = 0.0f;

        const float* __restrict__ Wp = g_Whc;
#pragma unroll 2
        for (int k = 0; k < UNITS; k += 4) {
            float w[4][4];
#pragma unroll
            for (int kk = 0; kk < 4; kk++)
#pragma unroll
                for (int g = 0; g < 4; g++)
                    w[kk][g] = Wp[(size_t)(k + kk) * G4 + g * UNITS + tid];
#pragma unroll
            for (int r = 0; r < 16; r++) {
                float4 cv = *(const float4*)&cs[r][k];
                float cc[4] = {cv.x, cv.y, cv.z, cv.w};
#pragma unroll
                for (int kk = 0; kk < 4; kk++)
#pragma unroll
                    for (int g = 0; g < 4; g++)
                        acc[r][g] = fmaf(cc[kk], w[kk][g], acc[r][g]);
            }
        }

        __syncthreads();              // all GEMM reads of cs done

#pragma unroll
        for (int r = 0; r < 16; r++) {
            size_t xbase = ((size_t)(b0 + r) * TT + t) * G4;
            float f  = sigf(acc[r][0] + g_Xp[xbase + 0 * UNITS + tid]);
            float ii = sigf(acc[r][1] + g_Xp[xbase + 1 * UNITS + tid]);
            float gg = sigf(acc[r][2] + g_Xp[xbase + 2 * UNITS + tid]);
            float oo = tanhf(acc[r][3] + g_Xp[xbase + 3 * UNITS + tid]);
            float cold = cs[r][tid];
            float cnew = fmaf(f, cold, ii * gg);
            cs[r][tid] = cnew;
            g_S[((size_t)(b0 + r) * TT + t) * UNITS + tid] = oo * tanhf(cnew);
        }
    }
}

// ---------------------------------------------------------------------------
// h[b,t,:] = tanh(S[b,t,:] @ U[t])   -- 49 independent 2048x256x256 GEMMs
// grid (32, 4, 49); 64x64 tile like above, strided A/C rows.
// ---------------------------------------------------------------------------
__global__ __launch_bounds__(256) void hproj(float* __restrict__ out) {
    __shared__ float As[16][64];
    __shared__ float Bs[16][64];
    int tid = threadIdx.x;
    int bm = blockIdx.x, bn = blockIdx.y, t = blockIdx.z;
    int tx = tid & 15, ty = tid >> 4;

    const size_t rowstride = (size_t)TT * UNITS;
    const float* Ab = g_S + (size_t)bm * 64 * rowstride + (size_t)t * UNITS;
    const float* Bb = g_U + (size_t)t * UNITS * UNITS + (size_t)bn * 64;

    int arow = tid >> 2;
    int acol = (tid & 3) * 4;
    int brow = tid >> 4;
    int bcol = (tid & 15) * 4;

    float acc[4][4] = {};

    for (int k0 = 0; k0 < UNITS; k0 += 16) {
        float4 av = *(const float4*)(Ab + (size_t)arow * rowstride + k0 + acol);
        float4 bv = *(const float4*)(Bb + (size_t)(k0 + brow) * UNITS + bcol);
        __syncthreads();
        As[acol + 0][arow] = av.x;
        As[acol + 1][arow] = av.y;
        As[acol + 2][arow] = av.z;
        As[acol + 3][arow] = av.w;
        *(float4*)&Bs[brow][bcol] = bv;
        __syncthreads();
#pragma unroll
        for (int k = 0; k < 16; k++) {
            float4 a = *(const float4*)&As[k][ty * 4];
            float4 b = *(const float4*)&Bs[k][tx * 4];
            float ar[4] = {a.x, a.y, a.z, a.w};
            float br[4] = {b.x, b.y, b.z, b.w};
#pragma unroll
            for (int r = 0; r < 4; r++)
#pragma unroll
                for (int c = 0; c < 4; c++)
                    acc[r][c] = fmaf(ar[r], br[c], acc[r][c]);
        }
    }
    // out[b][t][j], b = bm*64 + ty*4 + r, j = bn*64 + tx*4 + c
    float* Cb = out + (size_t)bm * 64 * rowstride + (size_t)t * UNITS + (size_t)bn * 64;
#pragma unroll
    for (int r = 0; r < 4; r++) {
        float4 o = make_float4(tanhf(acc[r][0]), tanhf(acc[r][1]),
                               tanhf(acc[r][2]), tanhf(acc[r][3]));
        *(float4*)(Cb + (size_t)(ty * 4 + r) * rowstride + tx * 4) = o;
    }
}

extern "C" void kernel_launch(void* const* d_in, const int* in_sizes, int n_in,
                              void* d_out, int out_size) {
    const float* x  = (const float*)d_in[0];
    const float* Wf = (const float*)d_in[1];
    const float* Wi = (const float*)d_in[2];
    const float* Wc = (const float*)d_in[3];
    const float* Wo = (const float*)d_in[4];
    const float* Q  = (const float*)d_in[5];
    float* out = (float*)d_out;

    build_U<<<dim3(TT, UNITS), 256>>>(Q);
    prep_W<<<(512 * UNITS + 255) / 256, 256>>>(Wf, Wi, Wc, Wo);
    gemm_xproj<<<dim3(BATCH * TT / 64, G4 / 64), 256>>>(x);
    recur<<<BATCH / 16, 256>>>();
    hproj<<<dim3(BATCH / 64, UNITS / 64, TT), 256>>>(out);
}

// round 2
// speedup vs baseline: 1.7227x; 1.7227x over previous
#include <cuda_runtime.h>
#include <math.h>
#include <stdint.h>

#define TT 49
#define UNITS 256
#define QN 9
#define DIMF 256
#define BATCH 2048
#define G4 1024
#define RS (TT * UNITS)          // 12544, row stride of x-flattened [b][t][*] tensors
#define PI_F 3.14159265358979f

// ---- static device scratch ----
__device__ float  g_U[(size_t)TT * UNITS * UNITS];   // [t][k][n]
__device__ float  g_Whx[(size_t)DIMF * G4];          // x-part weights [k][g*256+j]
__device__ float4 g_W4[(size_t)UNITS * UNITS];       // c-part weights, gate-packed [k*256+j] = (f,i,c,o)
__device__ float  g_Xp[(size_t)BATCH * TT * G4];     // gate-interleaved: [bt*1024 + j*4 + g]
__device__ float  g_S[(size_t)BATCH * TT * UNITS];   // [bt*256 + j]

__device__ __forceinline__ float sigf(float x) { return 1.0f / (1.0f + expf(-x)); }

__device__ __forceinline__ uint32_t f2tf(float x) {
    uint32_t r;
    asm("cvt.rna.tf32.f32 %0, %1;" : "=r"(r) : "f"(x));
    return r;
}

__device__ __forceinline__ void mma_tf32(float* c, const uint32_t* a, const uint32_t* b) {
    asm volatile(
        "mma.sync.aligned.m16n8k8.row.col.f32.tf32.tf32.f32 "
        "{%0,%1,%2,%3}, {%4,%5,%6,%7}, {%8,%9}, {%0,%1,%2,%3};\n"
        : "+f"(c[0]), "+f"(c[1]), "+f"(c[2]), "+f"(c[3])
        : "r"(a[0]), "r"(a[1]), "r"(a[2]), "r"(a[3]), "r"(b[0]), "r"(b[1]));
}

// ---------------------------------------------------------------------------
// U[t][k][n] = sum_q Q[k, n*9+q] * B[t][q]
// ---------------------------------------------------------------------------
__global__ void build_U(const float* __restrict__ Q) {
    int t = blockIdx.x, i = blockIdx.y, j = threadIdx.x;
    __shared__ float Bq[QN];
    if (threadIdx.x < QN) {
        int q = threadIdx.x;
        float tt = (float)t / (float)(TT - 1);
        float v;
        if (q == 0) v = 1.0f;
        else {
            int h = (q + 1) >> 1;
            float w = 2.0f * PI_F * (float)h * tt;
            v = 1.41421356237309515f * ((q & 1) ? sinf(w) : cosf(w));
        }
        Bq[q] = v;
    }
    __syncthreads();
    const float* qrow = Q + (size_t)i * (UNITS * QN) + (size_t)j * QN;
    float acc = 0.0f;
#pragma unroll
    for (int q = 0; q < QN; q++) acc = fmaf(qrow[q], Bq[q], acc);
    g_U[((size_t)t * UNITS + i) * UNITS + j] = acc;
}

// ---------------------------------------------------------------------------
// weight prep: c-rows -> gate-packed float4; x-rows -> [k][g*256+j]
// ---------------------------------------------------------------------------
__global__ void prep_W(const float* __restrict__ Wf, const float* __restrict__ Wi,
                       const float* __restrict__ Wc, const float* __restrict__ Wo) {
    int idx = blockIdx.x * blockDim.x + threadIdx.x;
    if (idx >= 512 * UNITS) return;
    int k = idx >> 8, j = idx & 255;
    float vf = Wf[idx], vi = Wi[idx], vc = Wc[idx], vo = Wo[idx];
    if (k < UNITS) {
        g_W4[(size_t)k * UNITS + j] = make_float4(vf, vi, vc, vo);
    } else {
        float* dst = g_Whx + (size_t)(k - UNITS) * G4;
        dst[0 * UNITS + j] = vf;
        dst[1 * UNITS + j] = vi;
        dst[2 * UNITS + j] = vc;
        dst[3 * UNITS + j] = vo;
    }
}

// ---------------------------------------------------------------------------
// tf32 MMA GEMM: Xp = X(100352 x 256) @ Whx(256 x 1024)
// block tile 128x128, K-stage 32, 8 warps (4x2), warp tile 32x64
// epilogue scatters into gate-interleaved g_Xp.
// ---------------------------------------------------------------------------
__global__ __launch_bounds__(256) void xproj_mma(const float* __restrict__ A) {
    __shared__ uint32_t As[128][36];
    __shared__ uint32_t Bs[32][136];
    int tid = threadIdx.x;
    int bm = blockIdx.x, bn = blockIdx.y;
    int w = tid >> 5, lane = tid & 31;
    int wm = (w & 3) * 32, wn = (w >> 2) * 64;
    int g = lane >> 2, tc = lane & 3;

    const float* Ab = A + (size_t)bm * 128 * DIMF;
    const float* Bb = g_Whx + (size_t)bn * 128;

    int ar0 = tid >> 3, ac = (tid & 7) * 4;    // A: rows ar0+32i, 8 float4/row
    int br0 = tid >> 5, bc = (tid & 31) * 4;   // B: rows br0+8i, 32 float4/row

    float c[2][8][4];
#pragma unroll
    for (int mi = 0; mi < 2; mi++)
#pragma unroll
        for (int ni = 0; ni < 8; ni++)
#pragma unroll
            for (int q = 0; q < 4; q++) c[mi][ni][q] = 0.0f;

    float4 ar[4], br[4];
#pragma unroll
    for (int i = 0; i < 4; i++) {
        ar[i] = *(const float4*)(Ab + (size_t)(ar0 + 32 * i) * DIMF + ac);
        br[i] = *(const float4*)(Bb + (size_t)(br0 + 8 * i) * G4 + bc);
    }

    for (int s = 0; s < 8; s++) {
        __syncthreads();
#pragma unroll
        for (int i = 0; i < 4; i++) {
            uint32_t* pa = &As[ar0 + 32 * i][ac];
            pa[0] = f2tf(ar[i].x); pa[1] = f2tf(ar[i].y);
            pa[2] = f2tf(ar[i].z); pa[3] = f2tf(ar[i].w);
            uint32_t* pb = &Bs[br0 + 8 * i][bc];
            pb[0] = f2tf(br[i].x); pb[1] = f2tf(br[i].y);
            pb[2] = f2tf(br[i].z); pb[3] = f2tf(br[i].w);
        }
        __syncthreads();
        if (s < 7) {
            int k0 = (s + 1) * 32;
#pragma unroll
            for (int i = 0; i < 4; i++) {
                ar[i] = *(const float4*)(Ab + (size_t)(ar0 + 32 * i) * DIMF + k0 + ac);
                br[i] = *(const float4*)(Bb + (size_t)(k0 + br0 + 8 * i) * G4 + bc);
            }
        }
#pragma unroll
        for (int kk = 0; kk < 4; kk++) {
            int k8 = kk * 8;
            uint32_t af[2][4];
#pragma unroll
            for (int mi = 0; mi < 2; mi++) {
                int r0 = wm + mi * 16 + g;
                af[mi][0] = As[r0][k8 + tc];
                af[mi][1] = As[r0 + 8][k8 + tc];
                af[mi][2] = As[r0][k8 + tc + 4];
                af[mi][3] = As[r0 + 8][k8 + tc + 4];
            }
            uint32_t bf[8][2];
#pragma unroll
            for (int ni = 0; ni < 8; ni++) {
                int nc = wn + ni * 8 + g;
                bf[ni][0] = Bs[k8 + tc][nc];
                bf[ni][1] = Bs[k8 + tc + 4][nc];
            }
#pragma unroll
            for (int mi = 0; mi < 2; mi++)
#pragma unroll
                for (int ni = 0; ni < 8; ni++)
                    mma_tf32(c[mi][ni], af[mi], bf[ni]);
        }
    }

    // epilogue: scatter to gate-interleaved layout [row*1024 + j*4 + gate]
#pragma unroll
    for (int mi = 0; mi < 2; mi++) {
#pragma unroll
        for (int ni = 0; ni < 8; ni++) {
            int row0 = bm * 128 + wm + mi * 16 + g;
            int n0 = bn * 128 + wn + ni * 8 + 2 * tc;
            int j2 = n0 & 255, gg = n0 >> 8;
            size_t base = (size_t)row0 * G4 + (size_t)j2 * 4 + gg;
            g_Xp[base] = c[mi][ni][0];
            g_Xp[base + 4] = c[mi][ni][1];
            size_t base2 = base + (size_t)8 * G4;
            g_Xp[base2] = c[mi][ni][2];
            g_Xp[base2 + 4] = c[mi][ni][3];
        }
    }
}

// ---------------------------------------------------------------------------
// Recurrence: 128 blocks x 16 rows, FFMA, gate-packed float4 weights.
// ---------------------------------------------------------------------------
__global__ __launch_bounds__(256) void recur() {
    int b0 = blockIdx.x * 16;
    int tid = threadIdx.x;
    __shared__ float cs[16][UNITS];
#pragma unroll
    for (int r = 0; r < 16; r++) cs[r][tid] = 0.0f;

    const float4* __restrict__ X4 = (const float4*)g_Xp;

    for (int t = 0; t < TT; t++) {
        __syncthreads();
        float acc[16][4];
#pragma unroll
        for (int r = 0; r < 16; r++)
#pragma unroll
            for (int q = 0; q < 4; q++) acc[r][q] = 0.0f;

#pragma unroll 2
        for (int k = 0; k < UNITS; k += 4) {
            float4 w0 = g_W4[(size_t)(k + 0) * UNITS + tid];
            float4 w1 = g_W4[(size_t)(k + 1) * UNITS + tid];
            float4 w2 = g_W4[(size_t)(k + 2) * UNITS + tid];
            float4 w3 = g_W4[(size_t)(k + 3) * UNITS + tid];
#pragma unroll
            for (int r = 0; r < 16; r++) {
                float4 cv = *(const float4*)&cs[r][k];
                acc[r][0] = fmaf(cv.x, w0.x, acc[r][0]);
                acc[r][1] = fmaf(cv.x, w0.y, acc[r][1]);
                acc[r][2] = fmaf(cv.x, w0.z, acc[r][2]);
                acc[r][3] = fmaf(cv.x, w0.w, acc[r][3]);
                acc[r][0] = fmaf(cv.y, w1.x, acc[r][0]);
                acc[r][1] = fmaf(cv.y, w1.y, acc[r][1]);
                acc[r][2] = fmaf(cv.y, w1.z, acc[r][2]);
                acc[r][3] = fmaf(cv.y, w1.w, acc[r][3]);
                acc[r][0] = fmaf(cv.z, w2.x, acc[r][0]);
                acc[r][1] = fmaf(cv.z, w2.y, acc[r][1]);
                acc[r][2] = fmaf(cv.z, w2.z, acc[r][2]);
                acc[r][3] = fmaf(cv.z, w2.w, acc[r][3]);
                acc[r][0] = fmaf(cv.w, w3.x, acc[r][0]);
                acc[r][1] = fmaf(cv.w, w3.y, acc[r][1]);
                acc[r][2] = fmaf(cv.w, w3.z, acc[r][2]);
                acc[r][3] = fmaf(cv.w, w3.w, acc[r][3]);
            }
        }

        __syncthreads();

#pragma unroll
        for (int r = 0; r < 16; r++) {
            float4 xg = X4[((size_t)(b0 + r) * TT + t) * UNITS + tid];
            float f  = sigf(acc[r][0] + xg.x);
            float ii = sigf(acc[r][1] + xg.y);
            float gg = sigf(acc[r][2] + xg.z);
            float oo = tanhf(acc[r][3] + xg.w);
            float cold = cs[r][tid];
            float cnew = fmaf(f, cold, ii * gg);
            cs[r][tid] = cnew;
            g_S[((size_t)(b0 + r) * TT + t) * UNITS + tid] = oo * tanhf(cnew);
        }
    }
}

// ---------------------------------------------------------------------------
// tf32 MMA: out[b,t,:] = tanh(S[b,t,:] @ U[t]); grid (16, 2, 49)
// ---------------------------------------------------------------------------
__global__ __launch_bounds__(256) void hproj_mma(float* __restrict__ out) {
    __shared__ uint32_t As[128][36];
    __shared__ uint32_t Bs[32][136];
    int tid = threadIdx.x;
    int bm = blockIdx.x, bn = blockIdx.y, t = blockIdx.z;
    int w = tid >> 5, lane = tid & 31;
    int wm = (w & 3) * 32, wn = (w >> 2) * 64;
    int g = lane >> 2, tc = lane & 3;

    const float* Ab = g_S + (size_t)bm * 128 * RS + (size_t)t * UNITS;
    const float* Bb = g_U + (size_t)t * UNITS * UNITS + (size_t)bn * 128;

    int ar0 = tid >> 3, ac = (tid & 7) * 4;
    int br0 = tid >> 5, bc = (tid & 31) * 4;

    float c[2][8][4];
#pragma unroll
    for (int mi = 0; mi < 2; mi++)
#pragma unroll
        for (int ni = 0; ni < 8; ni++)
#pragma unroll
            for (int q = 0; q < 4; q++) c[mi][ni][q] = 0.0f;

    float4 ar[4], br[4];
#pragma unroll
    for (int i = 0; i < 4; i++) {
        ar[i] = *(const float4*)(Ab + (size_t)(ar0 + 32 * i) * RS + ac);
        br[i] = *(const float4*)(Bb + (size_t)(br0 + 8 * i) * UNITS + bc);
    }

    for (int s = 0; s < 8; s++) {
        __syncthreads();
#pragma unroll
        for (int i = 0; i < 4; i++) {
            uint32_t* pa = &As[ar0 + 32 * i][ac];
            pa[0] = f2tf(ar[i].x); pa[1] = f2tf(ar[i].y);
            pa[2] = f2tf(ar[i].z); pa[3] = f2tf(ar[i].w);
            uint32_t* pb = &Bs[br0 + 8 * i][bc];
            pb[0] = f2tf(br[i].x); pb[1] = f2tf(br[i].y);
            pb[2] = f2tf(br[i].z); pb[3] = f2tf(br[i].w);
        }
        __syncthreads();
        if (s < 7) {
            int k0 = (s + 1) * 32;
#pragma unroll
            for (int i = 0; i < 4; i++) {
                ar[i] = *(const float4*)(Ab + (size_t)(ar0 + 32 * i) * RS + k0 + ac);
                br[i] = *(const float4*)(Bb + (size_t)(k0 + br0 + 8 * i) * UNITS + bc);
            }
        }
#pragma unroll
        for (int kk = 0; kk < 4; kk++) {
            int k8 = kk * 8;
            uint32_t af[2][4];
#pragma unroll
            for (int mi = 0; mi < 2; mi++) {
                int r0 = wm + mi * 16 + g;
                af[mi][0] = As[r0][k8 + tc];
                af[mi][1] = As[r0 + 8][k8 + tc];
                af[mi][2] = As[r0][k8 + tc + 4];
                af[mi][3] = As[r0 + 8][k8 + tc + 4];
            }
            uint32_t bf[8][2];
#pragma unroll
            for (int ni = 0; ni < 8; ni++) {
                int nc = wn + ni * 8 + g;
                bf[ni][0] = Bs[k8 + tc][nc];
                bf[ni][1] = Bs[k8 + tc + 4][nc];
            }
#pragma unroll
            for (int mi = 0; mi < 2; mi++)
#pragma unroll
                for (int ni = 0; ni < 8; ni++)
                    mma_tf32(c[mi][ni], af[mi], bf[ni]);
        }
    }

    float* Cb = out + (size_t)bm * 128 * RS + (size_t)t * UNITS + (size_t)bn * 128;
#pragma unroll
    for (int mi = 0; mi < 2; mi++) {
#pragma unroll
        for (int ni = 0; ni < 8; ni++) {
            int r0 = wm + mi * 16 + g;
            int col = wn + ni * 8 + 2 * tc;
            float2 v0 = make_float2(tanhf(c[mi][ni][0]), tanhf(c[mi][ni][1]));
            float2 v1 = make_float2(tanhf(c[mi][ni][2]), tanhf(c[mi][ni][3]));
            *(float2*)(Cb + (size_t)r0 * RS + col) = v0;
            *(float2*)(Cb + (size_t)(r0 + 8) * RS + col) = v1;
        }
    }
}

extern "C" void kernel_launch(void* const* d_in, const int* in_sizes, int n_in,
                              void* d_out, int out_size) {
    const float* x  = (const float*)d_in[0];
    const float* Wf = (const float*)d_in[1];
    const float* Wi = (const float*)d_in[2];
    const float* Wc = (const float*)d_in[3];
    const float* Wo = (const float*)d_in[4];
    const float* Q  = (const float*)d_in[5];
    float* out = (float*)d_out;

    build_U<<<dim3(TT, UNITS), 256>>>(Q);
    prep_W<<<(512 * UNITS + 255) / 256, 256>>>(Wf, Wi, Wc, Wo);
    xproj_mma<<<dim3(BATCH * TT / 128, G4 / 128), 256>>>(x);
    recur<<<BATCH / 16, 256>>>();
    hproj_mma<<<dim3(BATCH / 128, UNITS / 128, TT), 256>>>(out);
}

// round 5
// speedup vs baseline: 2.1184x; 1.2297x over previous
#include <cuda_runtime.h>
#include <math.h>
#include <stdint.h>

#define TT 49
#define UNITS 256
#define QN 9
#define DIMF 256
#define BATCH 2048
#define G4 1024
#define RS (TT * UNITS)
#define PI_F 3.14159265358979f

#define S_GS 1032               // gate tile row stride (floats)
#define S_CS 260                // c-state row stride (floats)
#define KT 32                   // 256 / 8 k-tiles
#define RECUR_SMEM ((16 * S_GS + 3 * 16 * S_CS) * 4)

// ---- static device scratch ----
__device__ float    g_U[(size_t)TT * UNITS * UNITS];   // [t][k][n]
__device__ float    g_Whx[(size_t)DIMF * G4];          // x-part weights [k][g*256+j]
__device__ uint32_t g_Wb[(size_t)UNITS * G4];          // c-part weights, tf32, MMA-fragment order
__device__ float    g_Xp[(size_t)BATCH * TT * G4];     // gate-interleaved [bt*1024 + j*4 + g]
__device__ float    g_S[(size_t)BATCH * TT * UNITS];   // [bt*256 + j]

__device__ __forceinline__ float sigf(float x) { return 1.0f / (1.0f + expf(-x)); }

__device__ __forceinline__ uint32_t f2tf(float x) {
    uint32_t r;
    asm("cvt.rna.tf32.f32 %0, %1;" : "=r"(r) : "f"(x));
    return r;
}

__device__ __forceinline__ void mma_tf32(float* c, const uint32_t* a, const uint32_t* b) {
    asm volatile(
        "mma.sync.aligned.m16n8k8.row.col.f32.tf32.tf32.f32 "
        "{%0,%1,%2,%3}, {%4,%5,%6,%7}, {%8,%9}, {%0,%1,%2,%3};\n"
        : "+f"(c[0]), "+f"(c[1]), "+f"(c[2]), "+f"(c[3])
        : "r"(a[0]), "r"(a[1]), "r"(a[2]), "r"(a[3]), "r"(b[0]), "r"(b[1]));
}

// ---------------------------------------------------------------------------
// U[t][k][n] = sum_q Q[k, n*9+q] * B[t][q]
// ---------------------------------------------------------------------------
__global__ void build_U(const float* __restrict__ Q) {
    int t = blockIdx.x, i = blockIdx.y, j = threadIdx.x;
    __shared__ float Bq[QN];
    if (threadIdx.x < QN) {
        int q = threadIdx.x;
        float tt = (float)t / (float)(TT - 1);
        float v;
        if (q == 0) v = 1.0f;
        else {
            int h = (q + 1) >> 1;
            float w = 2.0f * PI_F * (float)h * tt;
            v = 1.41421356237309515f * ((q & 1) ? sinf(w) : cosf(w));
        }
        Bq[q] = v;
    }
    __syncthreads();
    const float* qrow = Q + (size_t)i * (UNITS * QN) + (size_t)j * QN;
    float acc = 0.0f;
#pragma unroll
    for (int q = 0; q < QN; q++) acc = fmaf(qrow[q], Bq[q], acc);
    g_U[((size_t)t * UNITS + i) * UNITS + j] = acc;
}

// ---------------------------------------------------------------------------
// x-part weights -> [k][g*256+j]
// ---------------------------------------------------------------------------
__global__ void prep_Whx(const float* __restrict__ Wf, const float* __restrict__ Wi,
                         const float* __restrict__ Wc, const float* __restrict__ Wo) {
    int idx = blockIdx.x * blockDim.x + threadIdx.x;
    if (idx >= 256 * UNITS) return;
    int k = idx >> 8, j = idx & 255;
    int src = (k + 256) * UNITS + j;       // x-part = rows 256..511 of cat weight
    float* dst = g_Whx + (size_t)k * G4;
    dst[0 * UNITS + j] = Wf[src];
    dst[1 * UNITS + j] = Wi[src];
    dst[2 * UNITS + j] = Wc[src];
    dst[3 * UNITS + j] = Wo[src];
}

// ---------------------------------------------------------------------------
// c-part weights -> tf32, m16n8k8 B-fragment order.
// out idx = ((kt*128 + nt)*64 + lane*2 + e)
//   k = kt*8 + (lane&3) + 4e ; n = nt*8 + (lane>>2) ; j = n>>2 ; gate = n&3
// ---------------------------------------------------------------------------
__global__ void prep_Wb(const float* __restrict__ Wf, const float* __restrict__ Wi,
                        const float* __restrict__ Wc, const float* __restrict__ Wo) {
    int idx = blockIdx.x * blockDim.x + threadIdx.x;
    if (idx >= UNITS * G4) return;
    int e = idx & 1;
    int lane = (idx >> 1) & 31;
    int nt = (idx >> 6) & 127;
    int kt = idx >> 13;
    int k = kt * 8 + (lane & 3) + 4 * e;
    int n = nt * 8 + (lane >> 2);
    int j = n >> 2, gate = n & 3;
    const float* W = (gate == 0) ? Wf : (gate == 1) ? Wi : (gate == 2) ? Wc : Wo;
    g_Wb[idx] = f2tf(W[(size_t)k * UNITS + j]);   // c-part = rows 0..255
}

// ---------------------------------------------------------------------------
// tf32 MMA GEMM: Xp = X(100352 x 256) @ Whx(256 x 1024); gate-interleaved out
// ---------------------------------------------------------------------------
__global__ __launch_bounds__(256) void xproj_mma(const float* __restrict__ A) {
    __shared__ uint32_t As[128][36];
    __shared__ uint32_t Bs[32][136];
    int tid = threadIdx.x;
    int bm = blockIdx.x, bn = blockIdx.y;
    int w = tid >> 5, lane = tid & 31;
    int wm = (w & 3) * 32, wn = (w >> 2) * 64;
    int g = lane >> 2, tc = lane & 3;

    const float* Ab = A + (size_t)bm * 128 * DIMF;
    const float* Bb = g_Whx + (size_t)bn * 128;

    int ar0 = tid >> 3, ac = (tid & 7) * 4;
    int br0 = tid >> 5, bc = (tid & 31) * 4;

    float c[2][8][4];
#pragma unroll
    for (int mi = 0; mi < 2; mi++)
#pragma unroll
        for (int ni = 0; ni < 8; ni++)
#pragma unroll
            for (int q = 0; q < 4; q++) c[mi][ni][q] = 0.0f;

    float4 ar[4], br[4];
#pragma unroll
    for (int i = 0; i < 4; i++) {
        ar[i] = *(const float4*)(Ab + (size_t)(ar0 + 32 * i) * DIMF + ac);
        br[i] = *(const float4*)(Bb + (size_t)(br0 + 8 * i) * G4 + bc);
    }

    for (int s = 0; s < 8; s++) {
        __syncthreads();
#pragma unroll
        for (int i = 0; i < 4; i++) {
            uint32_t* pa = &As[ar0 + 32 * i][ac];
            pa[0] = f2tf(ar[i].x); pa[1] = f2tf(ar[i].y);
            pa[2] = f2tf(ar[i].z); pa[3] = f2tf(ar[i].w);
            uint32_t* pb = &Bs[br0 + 8 * i][bc];
            pb[0] = f2tf(br[i].x); pb[1] = f2tf(br[i].y);
            pb[2] = f2tf(br[i].z); pb[3] = f2tf(br[i].w);
        }
        __syncthreads();
        if (s < 7) {
            int k0 = (s + 1) * 32;
#pragma unroll
            for (int i = 0; i < 4; i++) {
                ar[i] = *(const float4*)(Ab + (size_t)(ar0 + 32 * i) * DIMF + k0 + ac);
                br[i] = *(const float4*)(Bb + (size_t)(k0 + br0 + 8 * i) * G4 + bc);
            }
        }
#pragma unroll
        for (int kk = 0; kk < 4; kk++) {
            int k8 = kk * 8;
            uint32_t af[2][4];
#pragma unroll
            for (int mi = 0; mi < 2; mi++) {
                int r0 = wm + mi * 16 + g;
                af[mi][0] = As[r0][k8 + tc];
                af[mi][1] = As[r0 + 8][k8 + tc];
                af[mi][2] = As[r0][k8 + tc + 4];
                af[mi][3] = As[r0 + 8][k8 + tc + 4];
            }
            uint32_t bf[8][2];
#pragma unroll
            for (int ni = 0; ni < 8; ni++) {
                int nc = wn + ni * 8 + g;
                bf[ni][0] = Bs[k8 + tc][nc];
                bf[ni][1] = Bs[k8 + tc + 4][nc];
            }
#pragma unroll
            for (int mi = 0; mi < 2; mi++)
#pragma unroll
                for (int ni = 0; ni < 8; ni++)
                    mma_tf32(c[mi][ni], af[mi], bf[ni]);
        }
    }

#pragma unroll
    for (int mi = 0; mi < 2; mi++) {
#pragma unroll
        for (int ni = 0; ni < 8; ni++) {
            int row0 = bm * 128 + wm + mi * 16 + g;
            int n0 = bn * 128 + wn + ni * 8 + 2 * tc;
            int j2 = n0 & 255, gg = n0 >> 8;
            size_t base = (size_t)row0 * G4 + (size_t)j2 * 4 + gg;
            g_Xp[base] = c[mi][ni][0];
            g_Xp[base + 4] = c[mi][ni][1];
            size_t base2 = base + (size_t)8 * G4;
            g_Xp[base2] = c[mi][ni][2];
            g_Xp[base2 + 4] = c[mi][ni][3];
        }
    }
}

// ---------------------------------------------------------------------------
// Tensor-core recurrence. 128 blocks x 16 batch rows, 8 warps.
// Per t: G(16x1024) = [c_hi + c_lo](tf32) @ Wb(tf32) via 2 MMAs/tile,
// then elementwise gates from smem-staged tile + Xp.
// ---------------------------------------------------------------------------
__global__ __launch_bounds__(256) void recur_mma() {
    extern __shared__ float sm[];
    float*    gs      = sm;                               // [16][S_GS]
    float*    cs_full = sm + 16 * S_GS;                   // [16][S_CS]
    uint32_t* cs_hi   = (uint32_t*)(cs_full + 16 * S_CS); // [16][S_CS]
    uint32_t* cs_lo   = cs_hi + 16 * S_CS;                // [16][S_CS]

    int tid = threadIdx.x;
    int w = tid >> 5, lane = tid & 31;
    int g = lane >> 2, tc = lane & 3;
    int b0 = blockIdx.x * 16;

#pragma unroll
    for (int p = 0; p < 16; p++) {
        cs_full[p * S_CS + tid] = 0.0f;
        cs_hi[p * S_CS + tid] = 0u;
        cs_lo[p * S_CS + tid] = 0u;
    }
    __syncthreads();

    const uint2* __restrict__ Wb = (const uint2*)g_Wb;
    const float4* __restrict__ Xp4 = (const float4*)g_Xp;

    for (int t = 0; t < TT; t++) {
        float acc[16][4];
#pragma unroll
        for (int ni = 0; ni < 16; ni++)
#pragma unroll
            for (int q = 0; q < 4; q++) acc[ni][q] = 0.0f;

#pragma unroll 2
        for (int kt = 0; kt < KT; kt++) {
            int k8 = kt * 8;
            uint2 bf[16];
#pragma unroll
            for (int ni = 0; ni < 16; ni++)
                bf[ni] = Wb[(size_t)((kt * 128) + w * 16 + ni) * 32 + lane];
            uint32_t ah[4], al[4];
            ah[0] = cs_hi[g * S_CS + k8 + tc];
            ah[1] = cs_hi[(g + 8) * S_CS + k8 + tc];
            ah[2] = cs_hi[g * S_CS + k8 + tc + 4];
            ah[3] = cs_hi[(g + 8) * S_CS + k8 + tc + 4];
            al[0] = cs_lo[g * S_CS + k8 + tc];
            al[1] = cs_lo[(g + 8) * S_CS + k8 + tc];
            al[2] = cs_lo[g * S_CS + k8 + tc + 4];
            al[3] = cs_lo[(g + 8) * S_CS + k8 + tc + 4];
#pragma unroll
            for (int ni = 0; ni < 16; ni++) {
                mma_tf32(acc[ni], ah, (const uint32_t*)&bf[ni]);
                mma_tf32(acc[ni], al, (const uint32_t*)&bf[ni]);
            }
        }

        // stage gate tile to smem (n ordering = j*4 + gate)
#pragma unroll
        for (int ni = 0; ni < 16; ni++) {
            int n0 = w * 128 + ni * 8 + 2 * tc;
            *(float2*)&gs[g * S_GS + n0]       = make_float2(acc[ni][0], acc[ni][1]);
            *(float2*)&gs[(g + 8) * S_GS + n0] = make_float2(acc[ni][2], acc[ni][3]);
        }
        __syncthreads();

#pragma unroll 4
        for (int p = 0; p < 16; p++) {
            float4 gv = *(const float4*)&gs[p * S_GS + 4 * tid];
            float4 xv = Xp4[((size_t)(b0 + p) * TT + t) * UNITS + tid];
            float f  = sigf(gv.x + xv.x);
            float i_ = sigf(gv.y + xv.y);
            float gg = sigf(gv.z + xv.z);
            float oo = tanhf(gv.w + xv.w);
            float cold = cs_full[p * S_CS + tid];
            float cnew = fmaf(f, cold, i_ * gg);
            cs_full[p * S_CS + tid] = cnew;
            uint32_t hi = f2tf(cnew);
            cs_hi[p * S_CS + tid] = hi;
            cs_lo[p * S_CS + tid] = f2tf(cnew - __uint_as_float(hi));
            g_S[((size_t)(b0 + p) * TT + t) * UNITS + tid] = oo * tanhf(cnew);
        }
        __syncthreads();
    }
}

// ---------------------------------------------------------------------------
// tf32 MMA: out[b,t,:] = tanh(S[b,t,:] @ U[t]); grid (16, 2, 49)
// ---------------------------------------------------------------------------
__global__ __launch_bounds__(256) void hproj_mma(float* __restrict__ out) {
    __shared__ uint32_t As[128][36];
    __shared__ uint32_t Bs[32][136];
    int tid = threadIdx.x;
    int bm = blockIdx.x, bn = blockIdx.y, t = blockIdx.z;
    int w = tid >> 5, lane = tid & 31;
    int wm = (w & 3) * 32, wn = (w >> 2) * 64;
    int g = lane >> 2, tc = lane & 3;

    const float* Ab = g_S + (size_t)bm * 128 * RS + (size_t)t * UNITS;
    const float* Bb = g_U + (size_t)t * UNITS * UNITS + (size_t)bn * 128;

    int ar0 = tid >> 3, ac = (tid & 7) * 4;
    int br0 = tid >> 5, bc = (tid & 31) * 4;

    float c[2][8][4];
#pragma unroll
    for (int mi = 0; mi < 2; mi++)
#pragma unroll
        for (int ni = 0; ni < 8; ni++)
#pragma unroll
            for (int q = 0; q < 4; q++) c[mi][ni][q] = 0.0f;

    float4 ar[4], br[4];
#pragma unroll
    for (int i = 0; i < 4; i++) {
        ar[i] = *(const float4*)(Ab + (size_t)(ar0 + 32 * i) * RS + ac);
        br[i] = *(const float4*)(Bb + (size_t)(br0 + 8 * i) * UNITS + bc);
    }

    for (int s = 0; s < 8; s++) {
        __syncthreads();
#pragma unroll
        for (int i = 0; i < 4; i++) {
            uint32_t* pa = &As[ar0 + 32 * i][ac];
            pa[0] = f2tf(ar[i].x); pa[1] = f2tf(ar[i].y);
            pa[2] = f2tf(ar[i].z); pa[3] = f2tf(ar[i].w);
            uint32_t* pb = &Bs[br0 + 8 * i][bc];
            pb[0] = f2tf(br[i].x); pb[1] = f2tf(br[i].y);
            pb[2] = f2tf(br[i].z); pb[3] = f2tf(br[i].w);
        }
        __syncthreads();
        if (s < 7) {
            int k0 = (s + 1) * 32;
#pragma unroll
            for (int i = 0; i < 4; i++) {
                ar[i] = *(const float4*)(Ab + (size_t)(ar0 + 32 * i) * RS + k0 + ac);
                br[i] = *(const float4*)(Bb + (size_t)(k0 + br0 + 8 * i) * UNITS + bc);
            }
        }
#pragma unroll
        for (int kk = 0; kk < 4; kk++) {
            int k8 = kk * 8;
            uint32_t af[2][4];
#pragma unroll
            for (int mi = 0; mi < 2; mi++) {
                int r0 = wm + mi * 16 + g;
                af[mi][0] = As[r0][k8 + tc];
                af[mi][1] = As[r0 + 8][k8 + tc];
                af[mi][2] = As[r0][k8 + tc + 4];
                af[mi][3] = As[r0 + 8][k8 + tc + 4];
            }
            uint32_t bf[8][2];
#pragma unroll
            for (int ni = 0; ni < 8; ni++) {
                int nc = wn + ni * 8 + g;
                bf[ni][0] = Bs[k8 + tc][nc];
                bf[ni][1] = Bs[k8 + tc + 4][nc];
            }
#pragma unroll
            for (int mi = 0; mi < 2; mi++)
#pragma unroll
                for (int ni = 0; ni < 8; ni++)
                    mma_tf32(c[mi][ni], af[mi], bf[ni]);
        }
    }

    float* Cb = out + (size_t)bm * 128 * RS + (size_t)t * UNITS + (size_t)bn * 128;
#pragma unroll
    for (int mi = 0; mi < 2; mi++) {
#pragma unroll
        for (int ni = 0; ni < 8; ni++) {
            int r0 = wm + mi * 16 + g;
            int col = wn + ni * 8 + 2 * tc;
            float2 v0 = make_float2(tanhf(c[mi][ni][0]), tanhf(c[mi][ni][1]));
            float2 v1 = make_float2(tanhf(c[mi][ni][2]), tanhf(c[mi][ni][3]));
            *(float2*)(Cb + (size_t)r0 * RS + col) = v0;
            *(float2*)(Cb + (size_t)(r0 + 8) * RS + col) = v1;
        }
    }
}

extern "C" void kernel_launch(void* const* d_in, const int* in_sizes, int n_in,
                              void* d_out, int out_size) {
    const float* x  = (const float*)d_in[0];
    const float* Wf = (const float*)d_in[1];
    const float* Wi = (const float*)d_in[2];
    const float* Wc = (const float*)d_in[3];
    const float* Wo = (const float*)d_in[4];
    const float* Q  = (const float*)d_in[5];
    float* out = (float*)d_out;

    cudaFuncSetAttribute(recur_mma, cudaFuncAttributeMaxDynamicSharedMemorySize, RECUR_SMEM);

    build_U<<<dim3(TT, UNITS), 256>>>(Q);
    prep_Whx<<<(256 * UNITS + 255) / 256, 256>>>(Wf, Wi, Wc, Wo);
    prep_Wb<<<(UNITS * G4 + 255) / 256, 256>>>(Wf, Wi, Wc, Wo);
    xproj_mma<<<dim3(BATCH * TT / 128, G4 / 128), 256>>>(x);
    recur_mma<<<BATCH / 16, 256, RECUR_SMEM>>>();
    hproj_mma<<<dim3(BATCH / 128, UNITS / 128, TT), 256>>>(out);
}